// round 13
// baseline (speedup 1.0000x reference)
#include <cuda_runtime.h>
#include <cuda_fp16.h>

// LBP forward: out = 7.5 + 0.5 * sum_p 2^p * tanh(5*(samp_p - cen_p))
//
// Stage: TWO zero-padded fp16 copies scaled by 5, PW=72 (8 left-pad cols so
// col w+8 (w mult of 8) is 16B-aligned):
//   copy1[pl][r][j] = 5 * x[pl][r-1][j-8]   (centers, dx=0 samples)
//   copyB[pl][r][j] = 5 * x[pl][r-1][j-9]   (dx=-1 aligned; dx=+1 = +1 u32)
// Main: thread = (n, f, row-pair, 8-wide span) = 16 outputs. Per tap per row:
//   center  = 1 aligned LDG.128 (copy1)
//   sample  = 1 aligned LDG.128 (copy1 or copyB) + 1 LDG.32 (+8 halfs)
//   dx=+1 window = u32 select {y,z,w,e}; dx<=0 window = {x,y,z,w}. No shifts,
//   no bounds checks, branchless (null taps duplicate center -> tanh(0)=0).

#define N_  32
#define D_  64
#define H_  56
#define W_  56
#define F_  128
#define P_  4
#define HW_ (H_ * W_)
#define PW  72
#define PH  58
#define PPLANE (PW * PH)                 // 4176 halfs
#define NPLANES (N_ * D_)                // 2048
#define SVOL (NPLANES * PPLANE)          // 8,552,448 halfs per copy

__device__ __align__(16) __half g2[2 * NPLANES * PPLANE];   // 34.2 MB

// ---------------- stage ----------------
#define CH_ 9
#define STAGE_TOTAL (NPLANES * PH * CH_)   // 1,069,056

__global__ __launch_bounds__(256) void lbp_stage_kernel(const float* __restrict__ in)
{
    int idx = blockIdx.x * 256 + threadIdx.x;
    if (idx >= STAGE_TOTAL) return;
    int k  = idx % CH_;            // 8-half chunk: padded cols 8k..8k+7
    int t  = idx / CH_;
    int r  = t % PH;
    int pl = t / PH;
    int row = r - 1;

    float wv[12];                  // wv[i] = x[8k-12+i]
#pragma unroll
    for (int i = 0; i < 12; i++) wv[i] = 0.f;

    if (row >= 0 && row < H_) {
        const float* __restrict__ rp = in + (size_t)pl * HW_ + row * W_;
        if (k >= 2) {                          // x[8k-12..8k-9]
            float4 a = *reinterpret_cast<const float4*>(rp + 8 * k - 12);
            wv[0] = a.x; wv[1] = a.y; wv[2] = a.z; wv[3] = a.w;
        }
        if (k >= 1 && k <= 7) {                // x[8k-8..8k-5], x[8k-4..8k-1]
            float4 b = *reinterpret_cast<const float4*>(rp + 8 * k - 8);
            wv[4] = b.x; wv[5] = b.y; wv[6] = b.z; wv[7] = b.w;
            float4 c = *reinterpret_cast<const float4*>(rp + 8 * k - 4);
            wv[8] = c.x; wv[9] = c.y; wv[10] = c.z; wv[11] = c.w;
        }
    }

    // copy1[8k+t] = 5*wv[4+t];  copyB[8k+t] = 5*wv[3+t]
    __half2 h1[4], hB[4];
#pragma unroll
    for (int q = 0; q < 4; q++) {
        h1[q] = __floats2half2_rn(5.f * wv[4 + 2 * q], 5.f * wv[5 + 2 * q]);
        hB[q] = __floats2half2_rn(5.f * wv[3 + 2 * q], 5.f * wv[4 + 2 * q]);
    }
    size_t off = (size_t)pl * PPLANE + r * PW + 8 * k;
    *reinterpret_cast<uint4*>(g2 + off)                = *reinterpret_cast<uint4*>(h1);
    *reinterpret_cast<uint4*>(g2 + (size_t)SVOL + off) = *reinterpret_cast<uint4*>(hB);
}

// ---------------- main ----------------
__device__ __forceinline__ __half2 tanh_h2u(unsigned v) {
    asm("tanh.approx.f16x2 %0, %0;" : "+r"(v));
    return *reinterpret_cast<__half2*>(&v);
}

#define RP_ 28     // row pairs
#define WS_ 7      // 8-wide spans
#define TOTAL_ (N_ * F_ * RP_ * WS_)   // 802,816 threads

__global__ __launch_bounds__(256) void lbp_main_kernel(
    const int* __restrict__ kern,   // (F,P,2)
    const int* __restrict__ pm,     // (F,P)
    float*     __restrict__ out)
{
    int idx = blockIdx.x * 256 + threadIdx.x;
    if (idx >= TOTAL_) return;

    int ws = idx % WS_;
    int t  = idx / WS_;
    int rp = t % RP_;
    t /= RP_;
    int f  = t & (F_ - 1);
    int n  = t >> 7;

    int r0 = rp * 2;
    int w  = ws * 8;

    int4 pmv = *reinterpret_cast<const int4*>(pm + f * P_);
    int4 k01 = *reinterpret_cast<const int4*>(kern + f * P_ * 2);
    int4 k23 = *reinterpret_cast<const int4*>(kern + f * P_ * 2 + 4);
    int cs[4]  = {pmv.x, pmv.y, pmv.z, pmv.w};
    int dys[4] = {k01.x - 1, k01.z - 1, k23.x - 1, k23.z - 1};
    int dxs[4] = {k01.y - 1, k01.w - 1, k23.y - 1, k23.w - 1};

    const int base  = n * D_ * PPLANE;
    const int rcoff = (r0 + 1) * PW + (w + 8);     // 16B-aligned column

    int coff[4], soff[4];
    bool sel1[4];                                   // dx == +1 ?
#pragma unroll
    for (int p = 0; p < P_; p++) {
        int dy = dys[p], dx = dxs[p];
        int pb = base + cs[p] * PPLANE + rcoff;
        coff[p] = pb;
        soff[p] = pb + dy * PW + ((dx != 0) ? SVOL : 0);
        sel1[p] = (dx > 0);
    }

    __half2 z = __floats2half2_rn(0.f, 0.f);
    __half2 acc[8];                                 // [row j][4 half2]
#pragma unroll
    for (int j = 0; j < 8; j++) acc[j] = z;

    const __half2 wp2s[4] = {
        __floats2half2_rn(0.5f, 0.5f), __floats2half2_rn(1.f, 1.f),
        __floats2half2_rn(2.f, 2.f),   __floats2half2_rn(4.f, 4.f)
    };

#pragma unroll
    for (int j = 0; j < 2; j++) {
        // batch all 12 loads for this row (MLP 12), all aligned
        uint4    cv[4], sv[4];
        unsigned ev[4];
#pragma unroll
        for (int p = 0; p < P_; p++) {
            cv[p] = *reinterpret_cast<const uint4*>(g2 + coff[p] + j * PW);
            sv[p] = *reinterpret_cast<const uint4*>(g2 + soff[p] + j * PW);
            ev[p] = *reinterpret_cast<const unsigned*>(g2 + soff[p] + j * PW + 8);
        }
#pragma unroll
        for (int p = 0; p < P_; p++) {
            // dx=+1 window is the same data advanced by one u32
            unsigned s0 = sel1[p] ? sv[p].y : sv[p].x;
            unsigned s1 = sel1[p] ? sv[p].z : sv[p].y;
            unsigned s2 = sel1[p] ? sv[p].w : sv[p].z;
            unsigned s3 = sel1[p] ? ev[p]   : sv[p].w;
            __half2 d0 = __hsub2(*reinterpret_cast<__half2*>(&s0),
                                 *reinterpret_cast<__half2*>(&cv[p].x));
            __half2 d1 = __hsub2(*reinterpret_cast<__half2*>(&s1),
                                 *reinterpret_cast<__half2*>(&cv[p].y));
            __half2 d2 = __hsub2(*reinterpret_cast<__half2*>(&s2),
                                 *reinterpret_cast<__half2*>(&cv[p].z));
            __half2 d3 = __hsub2(*reinterpret_cast<__half2*>(&s3),
                                 *reinterpret_cast<__half2*>(&cv[p].w));
            acc[j * 4 + 0] = __hfma2(wp2s[p], tanh_h2u(*reinterpret_cast<unsigned*>(&d0)), acc[j * 4 + 0]);
            acc[j * 4 + 1] = __hfma2(wp2s[p], tanh_h2u(*reinterpret_cast<unsigned*>(&d1)), acc[j * 4 + 1]);
            acc[j * 4 + 2] = __hfma2(wp2s[p], tanh_h2u(*reinterpret_cast<unsigned*>(&d2)), acc[j * 4 + 2]);
            acc[j * 4 + 3] = __hfma2(wp2s[p], tanh_h2u(*reinterpret_cast<unsigned*>(&d3)), acc[j * 4 + 3]);
        }
    }

    float* o = out + ((size_t)(n * F_ + f) * HW_ + r0 * W_ + w);
#pragma unroll
    for (int j = 0; j < 2; j++) {
        float2 q0 = __half22float2(acc[j * 4 + 0]);
        float2 q1 = __half22float2(acc[j * 4 + 1]);
        float2 q2 = __half22float2(acc[j * 4 + 2]);
        float2 q3 = __half22float2(acc[j * 4 + 3]);
        float* orow = o + j * W_;
        *reinterpret_cast<float4*>(orow) =
            make_float4(7.5f + q0.x, 7.5f + q0.y, 7.5f + q1.x, 7.5f + q1.y);
        *reinterpret_cast<float4*>(orow + 4) =
            make_float4(7.5f + q2.x, 7.5f + q2.y, 7.5f + q3.x, 7.5f + q3.y);
    }
}

extern "C" void kernel_launch(void* const* d_in, const int* in_sizes, int n_in,
                              void* d_out, int out_size)
{
    const float* in   = (const float*)d_in[0];
    const int*   kern = (const int*)d_in[1];
    const int*   pm   = (const int*)d_in[2];
    float*       out  = (float*)d_out;

    lbp_stage_kernel<<<(STAGE_TOTAL + 255) / 256, 256>>>(in);
    lbp_main_kernel<<<(TOTAL_ + 255) / 256, 256>>>(kern, pm, out);
}

// round 14
// speedup vs baseline: 1.2500x; 1.2500x over previous
#include <cuda_runtime.h>
#include <cuda_fp16.h>

// LBP forward: out = 7.5 + 0.5 * sum_p 2^p * tanh(5*(samp_p - cen_p))
//
// Stage (R12): TWO zero-padded fp16 copies scaled by 5 (PW=64 halfs = 128B/row):
//   copy1[pl][r][j] = 5 * x[pl][r-1][j-4]   (centers, dx=0 samples)
//   copyB[pl][r][j] = 5 * x[pl][r-1][j-5]   (dx=-1 at +0; dx=+1 at +2 cols)
// Main: thread = (n, f, 4-row block rb, quad q in 0..15). The 16 quads tile
//   one FULL 128B padded row, so warp lanes 0-15 sit in one row and 16-31 in
//   one other row: every LDG.64/LDG.32/STG touches exactly 2 cache lines
//   (minimum possible wavefronts). Quads q=0,15 cover pad cols: they compute
//   (in-bounds, garbage) but do not store.
//   Branchless taps: null taps re-read the center (L1 dup hit), tanh(0)=0.
//   All 12 loads of a row batched before math (MLP 12).

#define N_  32
#define D_  64
#define H_  56
#define W_  56
#define F_  128
#define P_  4
#define HW_ (H_ * W_)
#define PW  64
#define PH  58
#define PPLANE (PW * PH)                  // 3712 halfs
#define NPLANES (N_ * D_)                 // 2048
#define SVOL (NPLANES * PPLANE)           // halfs per copy (fits int)

__device__ __align__(16) __half g2[2 * NPLANES * PPLANE];   // 30.4 MB

// ---------------- stage ----------------
#define STAGE_TOTAL (NPLANES * PH * 8)

__global__ __launch_bounds__(256) void lbp_stage_kernel(const float* __restrict__ in)
{
    int idx = blockIdx.x * 256 + threadIdx.x;
    if (idx >= STAGE_TOTAL) return;
    int k  = idx & 7;
    int t  = idx >> 3;
    int r  = t % PH;
    int pl = t / PH;
    int row = r - 1;

    float wv[12];                 // wv[i] = x[8k-8+i]
#pragma unroll
    for (int i = 0; i < 12; i++) wv[i] = 0.f;

    if (row >= 0 && row < H_) {
        const float* __restrict__ rp = in + (size_t)pl * HW_ + row * W_;
        if (k >= 1) {
            float4 a = *reinterpret_cast<const float4*>(rp + 8 * k - 8);
            wv[0] = a.x; wv[1] = a.y; wv[2] = a.z; wv[3] = a.w;
            float4 b = *reinterpret_cast<const float4*>(rp + 8 * k - 4);
            wv[4] = b.x; wv[5] = b.y; wv[6] = b.z; wv[7] = b.w;
        }
        if (k <= 6) {
            float4 c = *reinterpret_cast<const float4*>(rp + 8 * k);
            wv[8] = c.x; wv[9] = c.y; wv[10] = c.z; wv[11] = c.w;
        }
    }

    __half2 h1[4], hB[4];
#pragma unroll
    for (int q = 0; q < 4; q++) {
        h1[q] = __floats2half2_rn(5.f * wv[4 + 2 * q], 5.f * wv[5 + 2 * q]);
        hB[q] = __floats2half2_rn(5.f * wv[3 + 2 * q], 5.f * wv[4 + 2 * q]);
    }
    size_t off = (size_t)pl * PPLANE + r * PW + 8 * k;
    *reinterpret_cast<uint4*>(g2 + off)                = *reinterpret_cast<uint4*>(h1);
    *reinterpret_cast<uint4*>(g2 + (size_t)SVOL + off) = *reinterpret_cast<uint4*>(hB);
}

// ---------------- main ----------------
__device__ __forceinline__ __half2 tanh_h2u(unsigned v) {
    asm("tanh.approx.f16x2 %0, %0;" : "+r"(v));
    return *reinterpret_cast<__half2*>(&v);
}

#define RB_ 14     // 4-row blocks per plane
#define NQ_ 16     // quads tiling the 128B padded row (q=0,15 are pad)
#define TOTAL_ (N_ * F_ * RB_ * NQ_)   // 917,504 threads

__global__ __launch_bounds__(256, 6) void lbp_main_kernel(
    const int* __restrict__ kern,   // (F,P,2)
    const int* __restrict__ pm,     // (F,P)
    float*     __restrict__ out)
{
    int idx = blockIdx.x * 256 + threadIdx.x;
    if (idx >= TOTAL_) return;

    int q  = idx & 15;              // padded cols 4q..4q+3
    int t  = idx >> 4;
    int rb = t % RB_;
    t /= RB_;
    int f  = t & (F_ - 1);
    int n  = t >> 7;

    int r0 = rb * 4;

    int4 pmv = *reinterpret_cast<const int4*>(pm + f * P_);
    int4 k01 = *reinterpret_cast<const int4*>(kern + f * P_ * 2);
    int4 k23 = *reinterpret_cast<const int4*>(kern + f * P_ * 2 + 4);
    int cs[4]  = {pmv.x, pmv.y, pmv.z, pmv.w};
    int dys[4] = {k01.x - 1, k01.z - 1, k23.x - 1, k23.z - 1};
    int dxs[4] = {k01.y - 1, k01.w - 1, k23.y - 1, k23.w - 1};

    const int nbase = n * D_ * PPLANE;
    const int rcoff = (r0 + 1) * PW + 4 * q;    // 8B-aligned padded column

    int coff[4], soff[4];
#pragma unroll
    for (int p = 0; p < P_; p++) {
        int dx = dxs[p], dy = dys[p];
        int pb = nbase + cs[p] * PPLANE + rcoff;
        coff[p] = pb;
        soff[p] = pb + dy * PW + ((dx != 0) ? SVOL : 0) + ((dx > 0) ? 2 : 0);
    }

    __half2 z = __floats2half2_rn(0.f, 0.f);
    __half2 acc[8];
#pragma unroll
    for (int j = 0; j < 8; j++) acc[j] = z;

    const __half2 wp2s[4] = {
        __floats2half2_rn(0.5f, 0.5f), __floats2half2_rn(1.f, 1.f),
        __floats2half2_rn(2.f, 2.f),   __floats2half2_rn(4.f, 4.f)
    };

#pragma unroll
    for (int j = 0; j < 4; j++) {
        uint2    cv[4];
        unsigned sa[4], sb[4];
#pragma unroll
        for (int p = 0; p < P_; p++) {
            cv[p] = *reinterpret_cast<const uint2*>(g2 + coff[p] + j * PW);
            sa[p] = *reinterpret_cast<const unsigned*>(g2 + soff[p] + j * PW);
            sb[p] = *reinterpret_cast<const unsigned*>(g2 + soff[p] + j * PW + 2);
        }
#pragma unroll
        for (int p = 0; p < P_; p++) {
            __half2 d0 = __hsub2(*reinterpret_cast<__half2*>(&sa[p]),
                                 *reinterpret_cast<__half2*>(&cv[p].x));
            __half2 d1 = __hsub2(*reinterpret_cast<__half2*>(&sb[p]),
                                 *reinterpret_cast<__half2*>(&cv[p].y));
            acc[j * 2 + 0] = __hfma2(wp2s[p], tanh_h2u(*reinterpret_cast<unsigned*>(&d0)), acc[j * 2 + 0]);
            acc[j * 2 + 1] = __hfma2(wp2s[p], tanh_h2u(*reinterpret_cast<unsigned*>(&d1)), acc[j * 2 + 1]);
        }
    }

    if (q >= 1 && q <= 14) {                     // data quads only
        int w = 4 * q - 4;                       // x column
        float* o = out + ((size_t)(n * F_ + f) * HW_ + r0 * W_ + w);
#pragma unroll
        for (int j = 0; j < 4; j++) {
            float2 lo = __half22float2(acc[j * 2 + 0]);
            float2 hi = __half22float2(acc[j * 2 + 1]);
            *reinterpret_cast<float4*>(o + j * W_) =
                make_float4(7.5f + lo.x, 7.5f + lo.y, 7.5f + hi.x, 7.5f + hi.y);
        }
    }
}

extern "C" void kernel_launch(void* const* d_in, const int* in_sizes, int n_in,
                              void* d_out, int out_size)
{
    const float* in   = (const float*)d_in[0];
    const int*   kern = (const int*)d_in[1];
    const int*   pm   = (const int*)d_in[2];
    float*       out  = (float*)d_out;

    lbp_stage_kernel<<<(STAGE_TOTAL + 255) / 256, 256>>>(in);
    lbp_main_kernel<<<(TOTAL_ + 255) / 256, 256>>>(kern, pm, out);
}